// round 1
// baseline (speedup 1.0000x reference)
#include <cuda_runtime.h>
#include <math.h>

#define B_   4
#define S_   2048
#define N_   2049
#define D_   512
#define R_   64
#define L_   2
#define WINW 32
#define E_   66      // 65 window edges + anchor
#define M_   (B_*N_)
#define SCALE 0.125f

// ---------------- scratch (no allocs allowed) ----------------
__device__ float g_val[M_*D_];
__device__ float g_dval[M_*D_];
__device__ float g_q[M_*R_];
__device__ float g_k[M_*R_];
__device__ float g_we[M_*E_];
__device__ float g_state[M_];
__device__ float g_dstate[M_];

// ---------------- block reduction (256 threads) ----------------
__device__ __forceinline__ float blkSum256(float v, float* sh) {
    int lane = threadIdx.x & 31, w = threadIdx.x >> 5;
    #pragma unroll
    for (int o = 16; o; o >>= 1) v += __shfl_xor_sync(0xffffffffu, v, o);
    if (lane == 0) sh[w] = v;
    __syncthreads();
    if (w == 0) {
        float x = (lane < 8) ? sh[lane] : 0.f;
        #pragma unroll
        for (int o = 4; o; o >>= 1) x += __shfl_xor_sync(0xffffffffu, x, o);
        if (lane == 0) sh[0] = x;
    }
    __syncthreads();
    float r = sh[0];
    __syncthreads();   // protect sh for next call
    return r;
}

// ---------------- K1: embedding + input LN + state proj ----------------
__global__ void k_embed(const int* __restrict__ ids, const float* __restrict__ emb,
                        const float* __restrict__ pos, const float* __restrict__ aval,
                        const float* __restrict__ ast,
                        const float* __restrict__ ing, const float* __restrict__ inb,
                        const float* __restrict__ spw, const float* __restrict__ spb) {
    __shared__ float sh[8];
    int bn = blockIdx.x;
    int b = bn / N_, n = bn % N_;
    float* vrow = g_val + (size_t)bn * D_;
    int t = threadIdx.x;
    if (n == 0) {
        vrow[t]       = aval[t];
        vrow[t + 256] = aval[t + 256];
        if (t == 0) g_state[bn] = ast[0];
        return;
    }
    int id = ids[b * S_ + (n - 1)];
    float x0 = emb[(size_t)id * D_ + t]       + pos[(size_t)(n - 1) * D_ + t];
    float x1 = emb[(size_t)id * D_ + t + 256] + pos[(size_t)(n - 1) * D_ + t + 256];
    float m  = blkSum256(x0 + x1, sh) * (1.f / D_);
    float d0 = x0 - m, d1 = x1 - m;
    float var = blkSum256(d0 * d0 + d1 * d1, sh) * (1.f / D_);
    float inv = rsqrtf(var + 1e-5f);
    float y0 = d0 * inv * ing[t]       + inb[t];
    float y1 = d1 * inv * ing[t + 256] + inb[t + 256];
    vrow[t] = y0; vrow[t + 256] = y1;
    float dp = blkSum256(y0 * spw[t] + y1 * spw[t + 256], sh);
    if (t == 0) g_state[bn] = dp + spb[0];
}

// ---------------- K2: q/k projection  [M,512] @ [512,64] x2 ----------------
// 64-row x 128-col tile (cols 0..63 = q, 64..127 = k), 256 threads, 8x4 microtile
__global__ void k_proj(const float* __restrict__ wq, const float* __restrict__ wk, int layer) {
    __shared__ float As[32][68];    // [k][row]
    __shared__ float Bs[32][132];   // [k][col]
    int m0 = blockIdx.x * 64;
    const float* wqL = wq + (size_t)layer * D_ * R_;
    const float* wkL = wk + (size_t)layer * D_ * R_;
    int t = threadIdx.x;
    int cg = t & 31;       // col group: 4 cols
    int rg = t >> 5;       // row group: 8 rows
    float acc[8][4];
    #pragma unroll
    for (int i = 0; i < 8; i++)
        #pragma unroll
        for (int j = 0; j < 4; j++) acc[i][j] = 0.f;

    for (int kc = 0; kc < D_; kc += 32) {
        #pragma unroll
        for (int i = t; i < 64 * 32; i += 256) {
            int row = i >> 5, kk = i & 31;
            int gr = m0 + row; if (gr >= M_) gr = M_ - 1;
            As[kk][row] = g_val[(size_t)gr * D_ + kc + kk];
        }
        #pragma unroll
        for (int i = t; i < 32 * 128; i += 256) {
            int kk = i >> 7, c = i & 127;
            Bs[kk][c] = (c < 64) ? wqL[(size_t)(kc + kk) * R_ + c]
                                 : wkL[(size_t)(kc + kk) * R_ + (c - 64)];
        }
        __syncthreads();
        #pragma unroll
        for (int kk = 0; kk < 32; kk++) {
            float a[8], bb[4];
            #pragma unroll
            for (int i = 0; i < 8; i++) a[i] = As[kk][rg * 8 + i];
            #pragma unroll
            for (int j = 0; j < 4; j++) bb[j] = Bs[kk][cg * 4 + j];
            #pragma unroll
            for (int i = 0; i < 8; i++)
                #pragma unroll
                for (int j = 0; j < 4; j++) acc[i][j] += a[i] * bb[j];
        }
        __syncthreads();
    }
    #pragma unroll
    for (int i = 0; i < 8; i++) {
        int gr = m0 + rg * 8 + i;
        if (gr >= M_) continue;
        #pragma unroll
        for (int j = 0; j < 4; j++) {
            int c = cg * 4 + j;
            if (c < 64) g_q[(size_t)gr * R_ + c]        = acc[i][j];
            else        g_k[(size_t)gr * R_ + (c - 64)] = acc[i][j];
        }
    }
}

// ---------------- K3: scores + signed-abs softmax + dstate ----------------
__device__ __forceinline__ bool edge_valid(int n, int w) {
    if (w < 65) { int p = n + w - WINW; return (p >= 0) && (p < N_); }
    return n > WINW;   // anchor edge
}
__device__ __forceinline__ float sgnf(float s) {
    return (s > 0.f) ? 1.f : ((s < 0.f) ? -1.f : 0.f);
}

__global__ void k_scores() {
    __shared__ float ks[96][68];   // k rows n0-32 .. n0+63 (clamped)
    __shared__ float qs[32][68];
    __shared__ float k0[64];
    __shared__ float st[97];       // staged state rows + st[96] = state[0]
    __shared__ float sc[32][68];
    int b  = blockIdx.y;
    int n0 = blockIdx.x * 32;
    int t  = threadIdx.x;
    size_t base = (size_t)b * N_;

    for (int i = t; i < 96 * 64; i += 256) {
        int r = i >> 6, rr = i & 63;
        int g = n0 - WINW + r; g = min(max(g, 0), N_ - 1);
        ks[r][rr] = g_k[(base + g) * R_ + rr];
    }
    for (int i = t; i < 32 * 64; i += 256) {
        int r = i >> 6, rr = i & 63;
        int g = n0 + r; if (g >= N_) g = N_ - 1;
        qs[r][rr] = g_q[(base + g) * R_ + rr];
    }
    if (t < 64) k0[t] = g_k[base * R_ + t];
    if (t < 96) { int g = min(max(n0 - WINW + t, 0), N_ - 1); st[t] = g_state[base + g]; }
    if (t == 96) st[96] = g_state[base];
    __syncthreads();

    // scores: 32 nodes x 66 edges
    for (int task = t; task < 32 * E_; task += 256) {
        int i = task / E_, w = task % E_;
        float acc = 0.f;
        if (w < 65) {
            int r = i + w;
            #pragma unroll
            for (int rr = 0; rr < 64; rr += 4) {
                float4 qv = *(const float4*)&qs[i][rr];
                float4 kv = *(const float4*)&ks[r][rr];
                acc += qv.x * kv.x + qv.y * kv.y + qv.z * kv.z + qv.w * kv.w;
            }
        } else {
            #pragma unroll
            for (int rr = 0; rr < 64; rr += 4) {
                float4 qv = *(const float4*)&qs[i][rr];
                float4 kv = *(const float4*)&k0[rr];
                acc += qv.x * kv.x + qv.y * kv.y + qv.z * kv.z + qv.w * kv.w;
            }
        }
        sc[i][w] = acc * SCALE;
    }
    __syncthreads();

    // softmax over |sc| per node (warp per node, 4 nodes per warp)
    int warp = t >> 5, lane = t & 31;
    for (int i = warp; i < 32; i += 8) {
        int n = n0 + i;
        if (n >= N_) continue;     // warp-uniform
        int w0 = lane, w1 = lane + 32, w2 = (lane < 2) ? 64 + lane : -1;
        float s0 = sc[i][w0], s1 = sc[i][w1];
        float s2 = (w2 >= 0) ? sc[i][w2] : 0.f;
        bool v0 = edge_valid(n, w0);
        bool v1 = edge_valid(n, w1);
        bool v2 = (w2 >= 0) ? edge_valid(n, w2) : false;
        float mx = fmaxf(v0 ? fabsf(s0) : -1e30f,
                   fmaxf(v1 ? fabsf(s1) : -1e30f,
                         v2 ? fabsf(s2) : -1e30f));
        #pragma unroll
        for (int o = 16; o; o >>= 1) mx = fmaxf(mx, __shfl_xor_sync(0xffffffffu, mx, o));
        float e0 = v0 ? expf(fabsf(s0) - mx) : 0.f;
        float e1 = v1 ? expf(fabsf(s1) - mx) : 0.f;
        float e2 = v2 ? expf(fabsf(s2) - mx) : 0.f;
        float sum = e0 + e1 + e2;
        #pragma unroll
        for (int o = 16; o; o >>= 1) sum += __shfl_xor_sync(0xffffffffu, sum, o);
        float invs = 1.f / sum;
        float we0 = sgnf(s0) * e0 * invs;
        float we1 = sgnf(s1) * e1 * invs;
        float we2 = sgnf(s2) * e2 * invs;
        size_t o_ = (base + n) * E_;
        g_we[o_ + w0] = we0;
        g_we[o_ + w1] = we1;
        if (w2 >= 0) g_we[o_ + w2] = we2;
        // dstate
        float ds = we0 * st[i + w0] + we1 * st[i + w1];
        if (lane == 0) ds += we2 * st[i + 64];   // w=64 window edge
        if (lane == 1) ds += we2 * st[96];       // w=65 anchor -> state[0]
        #pragma unroll
        for (int o = 16; o; o >>= 1) ds += __shfl_xor_sync(0xffffffffu, ds, o);
        if (lane == 0) g_dstate[base + n] = ds;
    }
}

// ---------------- K4: dval propagation ----------------
// 32 nodes x 64 d per block; window val rows staged in smem
__global__ void k_dval() {
    __shared__ float vs[96][68];
    __shared__ float wes[32][E_];
    __shared__ float v0s[64];
    int b  = blockIdx.z;
    int dc = blockIdx.y * 64;
    int n0 = blockIdx.x * 32;
    int t  = threadIdx.x;
    size_t base = (size_t)b * N_;

    for (int i = t; i < 96 * 64; i += 256) {
        int r = i >> 6, d = i & 63;
        int g = n0 - WINW + r; g = min(max(g, 0), N_ - 1);
        vs[r][d] = g_val[(base + g) * D_ + dc + d];
    }
    for (int i = t; i < 32 * E_; i += 256) {
        int r = i / E_, w = i % E_;
        int g = n0 + r; if (g >= N_) g = N_ - 1;
        wes[r][w] = g_we[(base + g) * E_ + w];
    }
    if (t < 64) v0s[t] = g_val[base * D_ + dc + t];
    __syncthreads();

    int i  = t >> 3;          // node (0..31)
    int d0 = (t & 7) * 8;     // 8 features
    float4 a0 = make_float4(0.f, 0.f, 0.f, 0.f);
    float4 a1 = make_float4(0.f, 0.f, 0.f, 0.f);
    #pragma unroll 5
    for (int w = 0; w < 65; w++) {
        float wv = wes[i][w];
        float4 p0 = *(const float4*)&vs[i + w][d0];
        float4 p1 = *(const float4*)&vs[i + w][d0 + 4];
        a0.x += wv * p0.x; a0.y += wv * p0.y; a0.z += wv * p0.z; a0.w += wv * p0.w;
        a1.x += wv * p1.x; a1.y += wv * p1.y; a1.z += wv * p1.z; a1.w += wv * p1.w;
    }
    {   // anchor edge
        float wv = wes[i][65];
        float4 p0 = *(const float4*)&v0s[d0];
        float4 p1 = *(const float4*)&v0s[d0 + 4];
        a0.x += wv * p0.x; a0.y += wv * p0.y; a0.z += wv * p0.z; a0.w += wv * p0.w;
        a1.x += wv * p1.x; a1.y += wv * p1.y; a1.z += wv * p1.z; a1.w += wv * p1.w;
    }
    int n = n0 + i;
    if (n < N_) {
        float* out = g_dval + (base + n) * D_ + dc + d0;
        *(float4*)out       = a0;
        *(float4*)(out + 4) = a1;
    }
}

// ---------------- K5: residual + LayerNorm + state update ----------------
__global__ void k_ln(const float* __restrict__ lng, const float* __restrict__ lnb, int layer) {
    __shared__ float sh[8];
    int bn = blockIdx.x;
    int t  = threadIdx.x;
    float* vrow = g_val  + (size_t)bn * D_;
    float* drow = g_dval + (size_t)bn * D_;
    const float* g = lng + (size_t)layer * D_;
    const float* bt = lnb + (size_t)layer * D_;
    float x0 = vrow[t]       + drow[t];
    float x1 = vrow[t + 256] + drow[t + 256];
    float m  = blkSum256(x0 + x1, sh) * (1.f / D_);
    float d0 = x0 - m, d1 = x1 - m;
    float var = blkSum256(d0 * d0 + d1 * d1, sh) * (1.f / D_);
    float inv = rsqrtf(var + 1e-5f);
    vrow[t]       = d0 * inv * g[t]       + bt[t];
    vrow[t + 256] = d1 * inv * g[t + 256] + bt[t + 256];
    if (t == 0) g_state[bn] += g_dstate[bn];
}

// ---------------- K6: write output (state then val) ----------------
__global__ void k_out(float* __restrict__ out) {
    int i = blockIdx.x * 256 + threadIdx.x;
    const int SN = M_;
    const int TOT = M_ + M_ * D_;
    if (i < SN) out[i] = g_state[i];
    else if (i < TOT) out[i] = g_val[i - SN];
}

// ---------------- host ----------------
extern "C" void kernel_launch(void* const* d_in, const int* in_sizes, int n_in,
                              void* d_out, int out_size) {
    const int*   ids  = (const int*)  d_in[0];
    const float* emb  = (const float*)d_in[1];
    const float* pos  = (const float*)d_in[2];
    const float* aval = (const float*)d_in[3];
    const float* ast  = (const float*)d_in[4];
    const float* ing  = (const float*)d_in[5];
    const float* inb  = (const float*)d_in[6];
    const float* spw  = (const float*)d_in[7];
    const float* spb  = (const float*)d_in[8];
    const float* wq   = (const float*)d_in[9];
    const float* wk   = (const float*)d_in[10];
    const float* lng  = (const float*)d_in[11];
    const float* lnb  = (const float*)d_in[12];
    float* out = (float*)d_out;

    k_embed<<<M_, 256>>>(ids, emb, pos, aval, ast, ing, inb, spw, spb);
    for (int l = 0; l < L_; l++) {
        k_proj  <<<(M_ + 63) / 64, 256>>>(wq, wk, l);
        k_scores<<<dim3(65, B_), 256>>>();
        k_dval  <<<dim3(65, 8, B_), 256>>>();
        k_ln    <<<M_, 256>>>(lng, lnb, l);
    }
    int total = M_ + M_ * D_;
    k_out<<<(total + 255) / 256, 256>>>(out);
}

// round 3
// speedup vs baseline: 1.3069x; 1.3069x over previous
#include <cuda_runtime.h>
#include <math.h>

#define B_   4
#define S_   2048
#define N_   2049
#define D_   512
#define R_   64
#define L_   2
#define WINW 32
#define E_   66      // 65 window edges + anchor
#define M_   (B_*N_)
#define SCALE 0.125f

// ---------------- scratch (no allocs allowed) ----------------
__device__ float g_val[M_*D_];
__device__ float g_dval[M_*D_];
__device__ float g_q[M_*R_];
__device__ float g_k[M_*R_];
__device__ float g_we[M_*E_];
__device__ float g_state[M_];
__device__ float g_dstate[M_];

// ---------------- block reduction (256 threads) ----------------
__device__ __forceinline__ float blkSum256(float v, float* sh) {
    int lane = threadIdx.x & 31, w = threadIdx.x >> 5;
    #pragma unroll
    for (int o = 16; o; o >>= 1) v += __shfl_xor_sync(0xffffffffu, v, o);
    if (lane == 0) sh[w] = v;
    __syncthreads();
    if (w == 0) {
        float x = (lane < 8) ? sh[lane] : 0.f;
        #pragma unroll
        for (int o = 4; o; o >>= 1) x += __shfl_xor_sync(0xffffffffu, x, o);
        if (lane == 0) sh[0] = x;
    }
    __syncthreads();
    float r = sh[0];
    __syncthreads();
    return r;
}

// ---------------- K1: embedding + input LN + state proj ----------------
__global__ void k_embed(const int* __restrict__ ids, const float* __restrict__ emb,
                        const float* __restrict__ pos, const float* __restrict__ aval,
                        const float* __restrict__ ast,
                        const float* __restrict__ ing, const float* __restrict__ inb,
                        const float* __restrict__ spw, const float* __restrict__ spb) {
    __shared__ float sh[8];
    int bn = blockIdx.x;
    int b = bn / N_, n = bn % N_;
    float* vrow = g_val + (size_t)bn * D_;
    int t = threadIdx.x;
    if (n == 0) {
        vrow[t]       = aval[t];
        vrow[t + 256] = aval[t + 256];
        if (t == 0) g_state[bn] = ast[0];
        return;
    }
    int id = ids[b * S_ + (n - 1)];
    float x0 = emb[(size_t)id * D_ + t]       + pos[(size_t)(n - 1) * D_ + t];
    float x1 = emb[(size_t)id * D_ + t + 256] + pos[(size_t)(n - 1) * D_ + t + 256];
    float m  = blkSum256(x0 + x1, sh) * (1.f / D_);
    float d0 = x0 - m, d1 = x1 - m;
    float var = blkSum256(d0 * d0 + d1 * d1, sh) * (1.f / D_);
    float inv = rsqrtf(var + 1e-5f);
    float y0 = d0 * inv * ing[t]       + inb[t];
    float y1 = d1 * inv * ing[t + 256] + inb[t + 256];
    vrow[t] = y0; vrow[t + 256] = y1;
    float dp = blkSum256(y0 * spw[t] + y1 * spw[t + 256], sh);
    if (t == 0) g_state[bn] = dp + spb[0];
}

// ---------------- K2: q/k projection  [M,512] @ [512,64] x2 ----------------
__global__ void k_proj(const float* __restrict__ wq, const float* __restrict__ wk, int layer) {
    __shared__ float As[32][68];
    __shared__ float Bs[32][132];
    int m0 = blockIdx.x * 64;
    const float* wqL = wq + (size_t)layer * D_ * R_;
    const float* wkL = wk + (size_t)layer * D_ * R_;
    int t = threadIdx.x;
    int cg = t & 31;
    int rg = t >> 5;
    float acc[8][4];
    #pragma unroll
    for (int i = 0; i < 8; i++)
        #pragma unroll
        for (int j = 0; j < 4; j++) acc[i][j] = 0.f;

    for (int kc = 0; kc < D_; kc += 32) {
        #pragma unroll
        for (int i = t; i < 64 * 32; i += 256) {
            int row = i >> 5, kk = i & 31;
            int gr = m0 + row; if (gr >= M_) gr = M_ - 1;
            As[kk][row] = g_val[(size_t)gr * D_ + kc + kk];
        }
        #pragma unroll
        for (int i = t; i < 32 * 128; i += 256) {
            int kk = i >> 7, c = i & 127;
            Bs[kk][c] = (c < 64) ? wqL[(size_t)(kc + kk) * R_ + c]
                                 : wkL[(size_t)(kc + kk) * R_ + (c - 64)];
        }
        __syncthreads();
        #pragma unroll
        for (int kk = 0; kk < 32; kk++) {
            float a[8], bb[4];
            #pragma unroll
            for (int i = 0; i < 8; i++) a[i] = As[kk][rg * 8 + i];
            #pragma unroll
            for (int j = 0; j < 4; j++) bb[j] = Bs[kk][cg * 4 + j];
            #pragma unroll
            for (int i = 0; i < 8; i++)
                #pragma unroll
                for (int j = 0; j < 4; j++) acc[i][j] += a[i] * bb[j];
        }
        __syncthreads();
    }
    #pragma unroll
    for (int i = 0; i < 8; i++) {
        int gr = m0 + rg * 8 + i;
        if (gr >= M_) continue;
        #pragma unroll
        for (int j = 0; j < 4; j++) {
            int c = cg * 4 + j;
            if (c < 64) g_q[(size_t)gr * R_ + c]        = acc[i][j];
            else        g_k[(size_t)gr * R_ + (c - 64)] = acc[i][j];
        }
    }
}

// ---------------- K3: scores + signed-abs softmax + dstate ----------------
__device__ __forceinline__ bool edge_valid(int n, int w) {
    if (w < 65) { int p = n + w - WINW; return (p >= 0) && (p < N_); }
    return n > WINW;
}
__device__ __forceinline__ float sgnf(float s) {
    return (s > 0.f) ? 1.f : ((s < 0.f) ? -1.f : 0.f);
}

#define KS_STR 65
__global__ void k_scores() {
    __shared__ float ks[96][KS_STR];
    __shared__ float qs[32][KS_STR];
    __shared__ float k0[64];
    __shared__ float st[97];
    __shared__ float sc[32][68];
    int b  = blockIdx.y;
    int n0 = blockIdx.x * 32;
    int t  = threadIdx.x;
    size_t base = (size_t)b * N_;

    for (int i = t; i < 96 * 64; i += 256) {
        int r = i >> 6, rr = i & 63;
        int g = n0 - WINW + r; g = min(max(g, 0), N_ - 1);
        ks[r][rr] = g_k[(base + g) * R_ + rr];
    }
    for (int i = t; i < 32 * 64; i += 256) {
        int r = i >> 6, rr = i & 63;
        int g = n0 + r; if (g >= N_) g = N_ - 1;
        qs[r][rr] = g_q[(base + g) * R_ + rr];
    }
    if (t < 64) k0[t] = g_k[base * R_ + t];
    if (t < 96) { int g = min(max(n0 - WINW + t, 0), N_ - 1); st[t] = g_state[base + g]; }
    if (t == 96) st[96] = g_state[base];
    __syncthreads();

    // --- blocked score pass: thread = 2 nodes x 4 edges, edges w in [0,64) ---
    {
        int ng2 = t >> 4;          // 0..15 -> i0 = 2*ng2
        int wg  = t & 15;          // 0..15 -> w0 = 4*wg
        int i0 = ng2 * 2, w0 = wg * 4;
        float acc[2][4];
        #pragma unroll
        for (int j = 0; j < 2; j++)
            #pragma unroll
            for (int l = 0; l < 4; l++) acc[j][l] = 0.f;
        #pragma unroll 4
        for (int rr = 0; rr < 64; rr++) {
            float q0 = qs[i0][rr];
            float q1 = qs[i0 + 1][rr];
            float kv[5];
            #pragma unroll
            for (int m = 0; m < 5; m++) kv[m] = ks[i0 + w0 + m][rr];
            #pragma unroll
            for (int l = 0; l < 4; l++) {
                acc[0][l] += q0 * kv[l];
                acc[1][l] += q1 * kv[l + 1];
            }
        }
        #pragma unroll
        for (int l = 0; l < 4; l++) {
            sc[i0][w0 + l]     = acc[0][l] * SCALE;
            sc[i0 + 1][w0 + l] = acc[1][l] * SCALE;
        }
    }
    // --- leftover edges: w=64 (window) and w=65 (anchor) ---
    if (t < 64) {
        int i = t >> 1, w = 64 + (t & 1);
        float acc = 0.f;
        if (w == 64) {
            #pragma unroll 8
            for (int rr = 0; rr < 64; rr++) acc += qs[i][rr] * ks[i + 64][rr];
        } else {
            #pragma unroll 8
            for (int rr = 0; rr < 64; rr++) acc += qs[i][rr] * k0[rr];
        }
        sc[i][w] = acc * SCALE;
    }
    __syncthreads();

    // softmax over |sc| per node (warp per node, 4 nodes per warp)
    int warp = t >> 5, lane = t & 31;
    for (int i = warp; i < 32; i += 8) {
        int n = n0 + i;
        if (n >= N_) continue;
        int w0 = lane, w1 = lane + 32, w2 = (lane < 2) ? 64 + lane : -1;
        float s0 = sc[i][w0], s1 = sc[i][w1];
        float s2 = (w2 >= 0) ? sc[i][w2] : 0.f;
        bool v0 = edge_valid(n, w0);
        bool v1 = edge_valid(n, w1);
        bool v2 = (w2 >= 0) ? edge_valid(n, w2) : false;
        float mx = fmaxf(v0 ? fabsf(s0) : -1e30f,
                   fmaxf(v1 ? fabsf(s1) : -1e30f,
                         v2 ? fabsf(s2) : -1e30f));
        #pragma unroll
        for (int o = 16; o; o >>= 1) mx = fmaxf(mx, __shfl_xor_sync(0xffffffffu, mx, o));
        float e0 = v0 ? expf(fabsf(s0) - mx) : 0.f;
        float e1 = v1 ? expf(fabsf(s1) - mx) : 0.f;
        float e2 = v2 ? expf(fabsf(s2) - mx) : 0.f;
        float sum = e0 + e1 + e2;
        #pragma unroll
        for (int o = 16; o; o >>= 1) sum += __shfl_xor_sync(0xffffffffu, sum, o);
        float invs = 1.f / sum;
        float we0 = sgnf(s0) * e0 * invs;
        float we1 = sgnf(s1) * e1 * invs;
        float we2 = sgnf(s2) * e2 * invs;
        size_t o_ = (base + n) * E_;
        g_we[o_ + w0] = we0;
        g_we[o_ + w1] = we1;
        if (w2 >= 0) g_we[o_ + w2] = we2;
        float ds = we0 * st[i + w0] + we1 * st[i + w1];
        if (lane == 0) ds += we2 * st[i + 64];
        if (lane == 1) ds += we2 * st[96];
        #pragma unroll
        for (int o = 16; o; o >>= 1) ds += __shfl_xor_sync(0xffffffffu, ds, o);
        if (lane == 0) g_dstate[base + n] = ds;
    }
}

// ---------------- K4: dval propagation (register-blocked) ----------------
// block = 64 nodes x 128 feats, 256 threads, thread = 4 nodes x 8 feats
#define DV_NODES 64
#define DV_FEATS 128
#define DV_ROWS  128
#define DV_VSTR  132
#define DV_WSTR  80
// dyn smem: vs[128][132] | wz[64][80] | wa[64] | v0s[128]
#define DV_SMEM_FLOATS (DV_ROWS*DV_VSTR + DV_NODES*DV_WSTR + DV_NODES + DV_FEATS)

__global__ void k_dval() {
    extern __shared__ float sm[];
    float* vs  = sm;                                 // [128][132]
    float* wz  = vs + DV_ROWS * DV_VSTR;             // [64][80], zero-padded
    float* wa  = wz + DV_NODES * DV_WSTR;            // [64] anchor weights
    float* v0s = wa + DV_NODES;                      // [128]

    int b  = blockIdx.z;
    int dc = blockIdx.y * DV_FEATS;
    int n0 = blockIdx.x * DV_NODES;
    int t  = threadIdx.x;
    size_t base = (size_t)b * N_;

    // stage vs rows (global nodes n0-32+row, clamped)
    for (int i = t; i < DV_ROWS * (DV_FEATS / 4); i += 256) {
        int row = i >> 5, c4 = i & 31;
        int g = min(max(n0 - WINW + row, 0), N_ - 1);
        float4 v = *(const float4*)&g_val[(base + g) * D_ + dc + c4 * 4];
        *(float4*)&vs[row * DV_VSTR + c4 * 4] = v;
    }
    // zero weight table
    for (int i = t; i < DV_NODES * DV_WSTR; i += 256) wz[i] = 0.f;
    if (t < 32) *(float4*)&v0s[t * 4] = *(const float4*)&g_val[base * D_ + dc + t * 4];
    __syncthreads();
    // fill weights: wz[node][w+8] = we[node][w], w in [0,65)
    for (int i = t; i < DV_NODES * 65; i += 256) {
        int node = i / 65, w = i % 65;
        int g = n0 + node; if (g >= N_) g = N_ - 1;
        wz[node * DV_WSTR + w + 8] = g_we[(base + g) * E_ + w];
    }
    if (t < DV_NODES) {
        int g = n0 + t; if (g >= N_) g = N_ - 1;
        wa[t] = g_we[(base + g) * E_ + 65];
    }
    __syncthreads();

    int fg = t & 15;          // feat group -> 8 feats
    int ng = t >> 4;          // node group -> 4 nodes
    int i0 = ng * 4;
    int f0 = fg * 8;

    float4 a0[4], a1[4];
    #pragma unroll
    for (int j = 0; j < 4; j++) {
        a0[j] = make_float4(0.f, 0.f, 0.f, 0.f);
        a1[j] = make_float4(0.f, 0.f, 0.f, 0.f);
    }

    // r = i0 + rr; weight for node (i0+j) is wz[i0+j][rr - j + 8]
    #pragma unroll 4
    for (int rr = 0; rr < 68; rr++) {
        int r = i0 + rr;
        float4 v0 = *(const float4*)&vs[r * DV_VSTR + f0];
        float4 v1 = *(const float4*)&vs[r * DV_VSTR + f0 + 4];
        #pragma unroll
        for (int j = 0; j < 4; j++) {
            float wt = wz[(i0 + j) * DV_WSTR + rr - j + 8];
            a0[j].x += wt * v0.x; a0[j].y += wt * v0.y;
            a0[j].z += wt * v0.z; a0[j].w += wt * v0.w;
            a1[j].x += wt * v1.x; a1[j].y += wt * v1.y;
            a1[j].z += wt * v1.z; a1[j].w += wt * v1.w;
        }
    }
    // anchor edge
    {
        float4 v0 = *(const float4*)&v0s[f0];
        float4 v1 = *(const float4*)&v0s[f0 + 4];
        #pragma unroll
        for (int j = 0; j < 4; j++) {
            float wt = wa[i0 + j];
            a0[j].x += wt * v0.x; a0[j].y += wt * v0.y;
            a0[j].z += wt * v0.z; a0[j].w += wt * v0.w;
            a1[j].x += wt * v1.x; a1[j].y += wt * v1.y;
            a1[j].z += wt * v1.z; a1[j].w += wt * v1.w;
        }
    }
    #pragma unroll
    for (int j = 0; j < 4; j++) {
        int n = n0 + i0 + j;
        if (n < N_) {
            float* out = g_dval + (base + n) * D_ + dc + f0;
            *(float4*)out       = a0[j];
            *(float4*)(out + 4) = a1[j];
        }
    }
}

// ---------------- K5: residual + LayerNorm + state update ----------------
// final layer writes directly into d_out (state block then val block)
__global__ void k_ln(const float* __restrict__ lng, const float* __restrict__ lnb,
                     int layer, float* __restrict__ out) {
    __shared__ float sh[8];
    int bn = blockIdx.x;
    int t  = threadIdx.x;
    float* vrow = g_val  + (size_t)bn * D_;
    float* drow = g_dval + (size_t)bn * D_;
    const float* g  = lng + (size_t)layer * D_;
    const float* bt = lnb + (size_t)layer * D_;
    float x0 = vrow[t]       + drow[t];
    float x1 = vrow[t + 256] + drow[t + 256];
    float m  = blkSum256(x0 + x1, sh) * (1.f / D_);
    float d0 = x0 - m, d1 = x1 - m;
    float var = blkSum256(d0 * d0 + d1 * d1, sh) * (1.f / D_);
    float inv = rsqrtf(var + 1e-5f);
    float y0 = d0 * inv * g[t]       + bt[t];
    float y1 = d1 * inv * g[t + 256] + bt[t + 256];
    float* vdst = out ? (out + M_ + (size_t)bn * D_) : vrow;
    vdst[t]       = y0;
    vdst[t + 256] = y1;
    if (t == 0) {
        float s = g_state[bn] + g_dstate[bn];
        if (out) out[bn] = s;
        else     g_state[bn] = s;
    }
}

// ---------------- host ----------------
extern "C" void kernel_launch(void* const* d_in, const int* in_sizes, int n_in,
                              void* d_out, int out_size) {
    const int*   ids  = (const int*)  d_in[0];
    const float* emb  = (const float*)d_in[1];
    const float* pos  = (const float*)d_in[2];
    const float* aval = (const float*)d_in[3];
    const float* ast  = (const float*)d_in[4];
    const float* ing  = (const float*)d_in[5];
    const float* inb  = (const float*)d_in[6];
    const float* spw  = (const float*)d_in[7];
    const float* spb  = (const float*)d_in[8];
    const float* wq   = (const float*)d_in[9];
    const float* wk   = (const float*)d_in[10];
    const float* lng  = (const float*)d_in[11];
    const float* lnb  = (const float*)d_in[12];
    float* out = (float*)d_out;

    const int dv_smem = DV_SMEM_FLOATS * 4;
    cudaFuncSetAttribute(k_dval, cudaFuncAttributeMaxDynamicSharedMemorySize, dv_smem);

    k_embed<<<M_, 256>>>(ids, emb, pos, aval, ast, ing, inb, spw, spb);
    for (int l = 0; l < L_; l++) {
        k_proj  <<<(M_ + 63) / 64, 256>>>(wq, wk, l);
        k_scores<<<dim3(65, B_), 256>>>();
        k_dval  <<<dim3((N_ + DV_NODES - 1) / DV_NODES, D_ / DV_FEATS, B_), 256, dv_smem>>>();
        k_ln    <<<M_, 256>>>(lng, lnb, l, (l == L_ - 1) ? out : nullptr);
    }
}

// round 4
// speedup vs baseline: 1.4244x; 1.0899x over previous
#include <cuda_runtime.h>
#include <math.h>

#define B_   4
#define S_   2048
#define N_   2049
#define D_   512
#define R_   64
#define L_   2
#define WINW 32
#define E_   66      // 65 window edges + anchor
#define M_   (B_*N_)
#define SCALE 0.125f

// ---------------- scratch (no allocs allowed) ----------------
__device__ float g_val[M_*D_];
__device__ float g_dval[M_*D_];
__device__ float g_q[M_*R_];
__device__ float g_k[M_*R_];
__device__ float g_we[M_*E_];
__device__ float g_state[M_];
__device__ float g_dstate[M_];

// ---------------- block reduction (256 threads) ----------------
__device__ __forceinline__ float blkSum256(float v, float* sh) {
    int lane = threadIdx.x & 31, w = threadIdx.x >> 5;
    #pragma unroll
    for (int o = 16; o; o >>= 1) v += __shfl_xor_sync(0xffffffffu, v, o);
    if (lane == 0) sh[w] = v;
    __syncthreads();
    if (w == 0) {
        float x = (lane < 8) ? sh[lane] : 0.f;
        #pragma unroll
        for (int o = 4; o; o >>= 1) x += __shfl_xor_sync(0xffffffffu, x, o);
        if (lane == 0) sh[0] = x;
    }
    __syncthreads();
    float r = sh[0];
    __syncthreads();
    return r;
}

// ---------------- K1: embedding + input LN + state proj ----------------
__global__ void k_embed(const int* __restrict__ ids, const float* __restrict__ emb,
                        const float* __restrict__ pos, const float* __restrict__ aval,
                        const float* __restrict__ ast,
                        const float* __restrict__ ing, const float* __restrict__ inb,
                        const float* __restrict__ spw, const float* __restrict__ spb) {
    __shared__ float sh[8];
    int bn = blockIdx.x;
    int b = bn / N_, n = bn % N_;
    float* vrow = g_val + (size_t)bn * D_;
    int t = threadIdx.x;
    if (n == 0) {
        vrow[t]       = aval[t];
        vrow[t + 256] = aval[t + 256];
        if (t == 0) g_state[bn] = ast[0];
        return;
    }
    int id = ids[b * S_ + (n - 1)];
    float x0 = emb[(size_t)id * D_ + t]       + pos[(size_t)(n - 1) * D_ + t];
    float x1 = emb[(size_t)id * D_ + t + 256] + pos[(size_t)(n - 1) * D_ + t + 256];
    float m  = blkSum256(x0 + x1, sh) * (1.f / D_);
    float d0 = x0 - m, d1 = x1 - m;
    float var = blkSum256(d0 * d0 + d1 * d1, sh) * (1.f / D_);
    float inv = rsqrtf(var + 1e-5f);
    float y0 = d0 * inv * ing[t]       + inb[t];
    float y1 = d1 * inv * ing[t + 256] + inb[t + 256];
    vrow[t] = y0; vrow[t + 256] = y1;
    float dp = blkSum256(y0 * spw[t] + y1 * spw[t + 256], sh);
    if (t == 0) g_state[bn] = dp + spb[0];
}

// ---------------- K2: q/k projection  [M,512] @ [512,128] ----------------
// 128 threads, 64-row x 128-col tile, 8x8 microtile (cols 0..63=q, 64..127=k)
__global__ __launch_bounds__(128) void k_proj(const float* __restrict__ wq,
                                              const float* __restrict__ wk, int layer) {
    __shared__ float As[64][36];    // [row][kk], float4-aligned rows (36*4=144B, mult of 16)
    __shared__ float Bs[32][132];   // [kk][col]
    int m0 = blockIdx.x * 64;
    const float* wqL = wq + (size_t)layer * D_ * R_;
    const float* wkL = wk + (size_t)layer * D_ * R_;
    int t  = threadIdx.x;
    int cg = t & 15;     // 8 cols each
    int rg = t >> 4;     // 8 rows each
    float acc[8][8];
    #pragma unroll
    for (int i = 0; i < 8; i++)
        #pragma unroll
        for (int j = 0; j < 8; j++) acc[i][j] = 0.f;

    for (int kc = 0; kc < D_; kc += 32) {
        // As: 64 rows x 32 k (float4 along k)
        #pragma unroll
        for (int i = t; i < 64 * 8; i += 128) {
            int row = i >> 3, kq = (i & 7) * 4;
            int gr = m0 + row; if (gr >= M_) gr = M_ - 1;
            float4 v = *(const float4*)&g_val[(size_t)gr * D_ + kc + kq];
            *(float4*)&As[row][kq] = v;
        }
        // Bs: 32 k x 128 cols (float4 along cols)
        #pragma unroll
        for (int i = t; i < 32 * 32; i += 128) {
            int kk = i >> 5, c4 = (i & 31) * 4;
            float4 v;
            if (c4 < 64) v = *(const float4*)&wqL[(size_t)(kc + kk) * R_ + c4];
            else         v = *(const float4*)&wkL[(size_t)(kc + kk) * R_ + (c4 - 64)];
            *(float4*)&Bs[kk][c4] = v;
        }
        __syncthreads();
        #pragma unroll 8
        for (int kk = 0; kk < 32; kk++) {
            float a[8];
            #pragma unroll
            for (int i = 0; i < 8; i++) a[i] = As[rg * 8 + i][kk];
            float4 b0 = *(const float4*)&Bs[kk][cg * 8];
            float4 b1 = *(const float4*)&Bs[kk][cg * 8 + 4];
            #pragma unroll
            for (int i = 0; i < 8; i++) {
                acc[i][0] += a[i] * b0.x; acc[i][1] += a[i] * b0.y;
                acc[i][2] += a[i] * b0.z; acc[i][3] += a[i] * b0.w;
                acc[i][4] += a[i] * b1.x; acc[i][5] += a[i] * b1.y;
                acc[i][6] += a[i] * b1.z; acc[i][7] += a[i] * b1.w;
            }
        }
        __syncthreads();
    }
    // store: cg<8 -> q cols cg*8..+7 ; cg>=8 -> k cols (cg-8)*8..+7
    #pragma unroll
    for (int i = 0; i < 8; i++) {
        int gr = m0 + rg * 8 + i;
        if (gr >= M_) continue;
        float4 o0 = make_float4(acc[i][0], acc[i][1], acc[i][2], acc[i][3]);
        float4 o1 = make_float4(acc[i][4], acc[i][5], acc[i][6], acc[i][7]);
        if (cg < 8) {
            float* dst = g_q + (size_t)gr * R_ + cg * 8;
            *(float4*)dst = o0; *(float4*)(dst + 4) = o1;
        } else {
            float* dst = g_k + (size_t)gr * R_ + (cg - 8) * 8;
            *(float4*)dst = o0; *(float4*)(dst + 4) = o1;
        }
    }
}

// ---------------- K3: scores + signed-abs softmax + dstate ----------------
__device__ __forceinline__ bool edge_valid(int n, int w) {
    if (w < 65) { int p = n + w - WINW; return (p >= 0) && (p < N_); }
    return n > WINW;
}
__device__ __forceinline__ float sgnf(float s) {
    return (s > 0.f) ? 1.f : ((s < 0.f) ? -1.f : 0.f);
}

#define KS_STR 65
__global__ void k_scores() {
    __shared__ float ks[96][KS_STR];
    __shared__ float qs[32][KS_STR];
    __shared__ float k0[64];
    __shared__ float st[97];
    __shared__ float sc[32][68];
    int b  = blockIdx.y;
    int n0 = blockIdx.x * 32;
    int t  = threadIdx.x;
    size_t base = (size_t)b * N_;

    for (int i = t; i < 96 * 64; i += 256) {
        int r = i >> 6, rr = i & 63;
        int g = n0 - WINW + r; g = min(max(g, 0), N_ - 1);
        ks[r][rr] = g_k[(base + g) * R_ + rr];
    }
    for (int i = t; i < 32 * 64; i += 256) {
        int r = i >> 6, rr = i & 63;
        int g = n0 + r; if (g >= N_) g = N_ - 1;
        qs[r][rr] = g_q[(base + g) * R_ + rr];
    }
    if (t < 64) k0[t] = g_k[base * R_ + t];
    if (t < 96) { int g = min(max(n0 - WINW + t, 0), N_ - 1); st[t] = g_state[base + g]; }
    if (t == 96) st[96] = g_state[base];
    __syncthreads();

    // blocked score pass: thread = 2 nodes x 4 edges, w in [0,64)
    {
        int ng2 = t >> 4;
        int wg  = t & 15;
        int i0 = ng2 * 2, w0 = wg * 4;
        float acc[2][4];
        #pragma unroll
        for (int j = 0; j < 2; j++)
            #pragma unroll
            for (int l = 0; l < 4; l++) acc[j][l] = 0.f;
        #pragma unroll 4
        for (int rr = 0; rr < 64; rr++) {
            float q0 = qs[i0][rr];
            float q1 = qs[i0 + 1][rr];
            float kv[5];
            #pragma unroll
            for (int m = 0; m < 5; m++) kv[m] = ks[i0 + w0 + m][rr];
            #pragma unroll
            for (int l = 0; l < 4; l++) {
                acc[0][l] += q0 * kv[l];
                acc[1][l] += q1 * kv[l + 1];
            }
        }
        #pragma unroll
        for (int l = 0; l < 4; l++) {
            sc[i0][w0 + l]     = acc[0][l] * SCALE;
            sc[i0 + 1][w0 + l] = acc[1][l] * SCALE;
        }
    }
    if (t < 64) {
        int i = t >> 1, w = 64 + (t & 1);
        float acc = 0.f;
        if (w == 64) {
            #pragma unroll 8
            for (int rr = 0; rr < 64; rr++) acc += qs[i][rr] * ks[i + 64][rr];
        } else {
            #pragma unroll 8
            for (int rr = 0; rr < 64; rr++) acc += qs[i][rr] * k0[rr];
        }
        sc[i][w] = acc * SCALE;
    }
    __syncthreads();

    int warp = t >> 5, lane = t & 31;
    for (int i = warp; i < 32; i += 8) {
        int n = n0 + i;
        if (n >= N_) continue;
        int w0 = lane, w1 = lane + 32, w2 = (lane < 2) ? 64 + lane : -1;
        float s0 = sc[i][w0], s1 = sc[i][w1];
        float s2 = (w2 >= 0) ? sc[i][w2] : 0.f;
        bool v0 = edge_valid(n, w0);
        bool v1 = edge_valid(n, w1);
        bool v2 = (w2 >= 0) ? edge_valid(n, w2) : false;
        float mx = fmaxf(v0 ? fabsf(s0) : -1e30f,
                   fmaxf(v1 ? fabsf(s1) : -1e30f,
                         v2 ? fabsf(s2) : -1e30f));
        #pragma unroll
        for (int o = 16; o; o >>= 1) mx = fmaxf(mx, __shfl_xor_sync(0xffffffffu, mx, o));
        float e0 = v0 ? expf(fabsf(s0) - mx) : 0.f;
        float e1 = v1 ? expf(fabsf(s1) - mx) : 0.f;
        float e2 = v2 ? expf(fabsf(s2) - mx) : 0.f;
        float sum = e0 + e1 + e2;
        #pragma unroll
        for (int o = 16; o; o >>= 1) sum += __shfl_xor_sync(0xffffffffu, sum, o);
        float invs = 1.f / sum;
        float we0 = sgnf(s0) * e0 * invs;
        float we1 = sgnf(s1) * e1 * invs;
        float we2 = sgnf(s2) * e2 * invs;
        size_t o_ = (base + n) * E_;
        g_we[o_ + w0] = we0;
        g_we[o_ + w1] = we1;
        if (w2 >= 0) g_we[o_ + w2] = we2;
        float ds = we0 * st[i + w0] + we1 * st[i + w1];
        if (lane == 0) ds += we2 * st[i + 64];
        if (lane == 1) ds += we2 * st[96];
        #pragma unroll
        for (int o = 16; o; o >>= 1) ds += __shfl_xor_sync(0xffffffffu, ds, o);
        if (lane == 0) g_dstate[base + n] = ds;
    }
}

// ---------------- K4: dval propagation (register-blocked) ----------------
#define DV_NODES 64
#define DV_FEATS 128
#define DV_ROWS  128
#define DV_VSTR  132
#define DV_WSTR  80
#define DV_SMEM_FLOATS (DV_ROWS*DV_VSTR + DV_NODES*DV_WSTR + DV_NODES + DV_FEATS)

__global__ __launch_bounds__(256, 2) void k_dval() {
    extern __shared__ float sm[];
    float* vs  = sm;                                 // [128][132]
    float* wz  = vs + DV_ROWS * DV_VSTR;             // [64][80], zero-padded
    float* wa  = wz + DV_NODES * DV_WSTR;            // [64]
    float* v0s = wa + DV_NODES;                      // [128]

    int b  = blockIdx.z;
    int dc = blockIdx.y * DV_FEATS;
    int n0 = blockIdx.x * DV_NODES;
    int t  = threadIdx.x;
    size_t base = (size_t)b * N_;

    for (int i = t; i < DV_ROWS * (DV_FEATS / 4); i += 256) {
        int row = i >> 5, c4 = i & 31;
        int g = min(max(n0 - WINW + row, 0), N_ - 1);
        float4 v = *(const float4*)&g_val[(base + g) * D_ + dc + c4 * 4];
        *(float4*)&vs[row * DV_VSTR + c4 * 4] = v;
    }
    for (int i = t; i < DV_NODES * DV_WSTR; i += 256) wz[i] = 0.f;
    if (t < 32) *(float4*)&v0s[t * 4] = *(const float4*)&g_val[base * D_ + dc + t * 4];
    __syncthreads();
    for (int i = t; i < DV_NODES * 65; i += 256) {
        int node = i / 65, w = i % 65;
        int g = n0 + node; if (g >= N_) g = N_ - 1;
        wz[node * DV_WSTR + w + 8] = g_we[(base + g) * E_ + w];
    }
    if (t < DV_NODES) {
        int g = n0 + t; if (g >= N_) g = N_ - 1;
        wa[t] = g_we[(base + g) * E_ + 65];
    }
    __syncthreads();

    int fg = t & 15;
    int ng = t >> 4;
    int i0 = ng * 4;
    int f0 = fg * 8;

    float4 a0[4], a1[4];
    #pragma unroll
    for (int j = 0; j < 4; j++) {
        a0[j] = make_float4(0.f, 0.f, 0.f, 0.f);
        a1[j] = make_float4(0.f, 0.f, 0.f, 0.f);
    }

    #pragma unroll 4
    for (int rr = 0; rr < 68; rr++) {
        float wt[4];
        #pragma unroll
        for (int j = 0; j < 4; j++) wt[j] = wz[(i0 + j) * DV_WSTR + rr - j + 8];
        int r = i0 + rr;
        float4 v0 = *(const float4*)&vs[r * DV_VSTR + f0];
        float4 v1 = *(const float4*)&vs[r * DV_VSTR + f0 + 4];
        #pragma unroll
        for (int j = 0; j < 4; j++) {
            a0[j].x += wt[j] * v0.x; a0[j].y += wt[j] * v0.y;
            a0[j].z += wt[j] * v0.z; a0[j].w += wt[j] * v0.w;
            a1[j].x += wt[j] * v1.x; a1[j].y += wt[j] * v1.y;
            a1[j].z += wt[j] * v1.z; a1[j].w += wt[j] * v1.w;
        }
    }
    {
        float4 v0 = *(const float4*)&v0s[f0];
        float4 v1 = *(const float4*)&v0s[f0 + 4];
        #pragma unroll
        for (int j = 0; j < 4; j++) {
            float wt = wa[i0 + j];
            a0[j].x += wt * v0.x; a0[j].y += wt * v0.y;
            a0[j].z += wt * v0.z; a0[j].w += wt * v0.w;
            a1[j].x += wt * v1.x; a1[j].y += wt * v1.y;
            a1[j].z += wt * v1.z; a1[j].w += wt * v1.w;
        }
    }
    #pragma unroll
    for (int j = 0; j < 4; j++) {
        int n = n0 + i0 + j;
        if (n < N_) {
            float* out = g_dval + (base + n) * D_ + dc + f0;
            *(float4*)out       = a0[j];
            *(float4*)(out + 4) = a1[j];
        }
    }
}

// ---------------- K5: residual + LayerNorm + state update ----------------
__global__ void k_ln(const float* __restrict__ lng, const float* __restrict__ lnb,
                     int layer, float* __restrict__ out) {
    __shared__ float sh[8];
    int bn = blockIdx.x;
    int t  = threadIdx.x;
    float* vrow = g_val  + (size_t)bn * D_;
    float* drow = g_dval + (size_t)bn * D_;
    const float* g  = lng + (size_t)layer * D_;
    const float* bt = lnb + (size_t)layer * D_;
    float x0 = vrow[t]       + drow[t];
    float x1 = vrow[t + 256] + drow[t + 256];
    float m  = blkSum256(x0 + x1, sh) * (1.f / D_);
    float d0 = x0 - m, d1 = x1 - m;
    float var = blkSum256(d0 * d0 + d1 * d1, sh) * (1.f / D_);
    float inv = rsqrtf(var + 1e-5f);
    float y0 = d0 * inv * g[t]       + bt[t];
    float y1 = d1 * inv * g[t + 256] + bt[t + 256];
    float* vdst = out ? (out + M_ + (size_t)bn * D_) : vrow;
    vdst[t]       = y0;
    vdst[t + 256] = y1;
    if (t == 0) {
        float s = g_state[bn] + g_dstate[bn];
        if (out) out[bn] = s;
        else     g_state[bn] = s;
    }
}

// ---------------- host ----------------
extern "C" void kernel_launch(void* const* d_in, const int* in_sizes, int n_in,
                              void* d_out, int out_size) {
    const int*   ids  = (const int*)  d_in[0];
    const float* emb  = (const float*)d_in[1];
    const float* pos  = (const float*)d_in[2];
    const float* aval = (const float*)d_in[3];
    const float* ast  = (const float*)d_in[4];
    const float* ing  = (const float*)d_in[5];
    const float* inb  = (const float*)d_in[6];
    const float* spw  = (const float*)d_in[7];
    const float* spb  = (const float*)d_in[8];
    const float* wq   = (const float*)d_in[9];
    const float* wk   = (const float*)d_in[10];
    const float* lng  = (const float*)d_in[11];
    const float* lnb  = (const float*)d_in[12];
    float* out = (float*)d_out;

    const int dv_smem = DV_SMEM_FLOATS * 4;
    cudaFuncSetAttribute(k_dval, cudaFuncAttributeMaxDynamicSharedMemorySize, dv_smem);

    k_embed<<<M_, 256>>>(ids, emb, pos, aval, ast, ing, inb, spw, spb);
    for (int l = 0; l < L_; l++) {
        k_proj  <<<(M_ + 63) / 64, 128>>>(wq, wk, l);
        k_scores<<<dim3(65, B_), 256>>>();
        k_dval  <<<dim3((N_ + DV_NODES - 1) / DV_NODES, D_ / DV_FEATS, B_), 256, dv_smem>>>();
        k_ln    <<<M_, 256>>>(lng, lnb, l, (l == L_ - 1) ? out : nullptr);
    }
}

// round 6
// speedup vs baseline: 1.5871x; 1.1142x over previous
#include <cuda_runtime.h>
#include <math.h>

#define B_   4
#define S_   2048
#define N_   2049
#define D_   512
#define R_   64
#define L_   2
#define WINW 32
#define E_   66      // 65 window edges + anchor
#define M_   (B_*N_)
#define SCALE 0.125f

// ---------------- scratch (no allocs allowed) ----------------
__device__ float g_val[M_*D_];
__device__ float g_dval[M_*D_];
__device__ float g_q[M_*R_];
__device__ float g_k[M_*R_];
__device__ float g_we[M_*E_];
__device__ float g_state[M_];
__device__ float g_dstate[M_];

// ---------------- block reduction (256 threads) ----------------
__device__ __forceinline__ float blkSum256(float v, float* sh) {
    int lane = threadIdx.x & 31, w = threadIdx.x >> 5;
    #pragma unroll
    for (int o = 16; o; o >>= 1) v += __shfl_xor_sync(0xffffffffu, v, o);
    if (lane == 0) sh[w] = v;
    __syncthreads();
    if (w == 0) {
        float x = (lane < 8) ? sh[lane] : 0.f;
        #pragma unroll
        for (int o = 4; o; o >>= 1) x += __shfl_xor_sync(0xffffffffu, x, o);
        if (lane == 0) sh[0] = x;
    }
    __syncthreads();
    float r = sh[0];
    __syncthreads();
    return r;
}

// ---------------- K1: embedding + input LN + state proj ----------------
__global__ void k_embed(const int* __restrict__ ids, const float* __restrict__ emb,
                        const float* __restrict__ pos, const float* __restrict__ aval,
                        const float* __restrict__ ast,
                        const float* __restrict__ ing, const float* __restrict__ inb,
                        const float* __restrict__ spw, const float* __restrict__ spb) {
    __shared__ float sh[8];
    int bn = blockIdx.x;
    int b = bn / N_, n = bn % N_;
    float* vrow = g_val + (size_t)bn * D_;
    int t = threadIdx.x;
    if (n == 0) {
        vrow[t]       = aval[t];
        vrow[t + 256] = aval[t + 256];
        if (t == 0) g_state[bn] = ast[0];
        return;
    }
    int id = ids[b * S_ + (n - 1)];
    float x0 = emb[(size_t)id * D_ + t]       + pos[(size_t)(n - 1) * D_ + t];
    float x1 = emb[(size_t)id * D_ + t + 256] + pos[(size_t)(n - 1) * D_ + t + 256];
    float m  = blkSum256(x0 + x1, sh) * (1.f / D_);
    float d0 = x0 - m, d1 = x1 - m;
    float var = blkSum256(d0 * d0 + d1 * d1, sh) * (1.f / D_);
    float inv = rsqrtf(var + 1e-5f);
    float y0 = d0 * inv * ing[t]       + inb[t];
    float y1 = d1 * inv * ing[t + 256] + inb[t + 256];
    vrow[t] = y0; vrow[t + 256] = y1;
    float dp = blkSum256(y0 * spw[t] + y1 * spw[t + 256], sh);
    if (t == 0) g_state[bn] = dp + spb[0];
}

// ---------------- K2: q/k projection  [M,512] @ [512,128] ----------------
// 128 threads, 32-row x 128-col tile, thread = 4 rows x (4 q-cols + 4 k-cols)
__global__ __launch_bounds__(128) void k_proj(const float* __restrict__ wq,
                                              const float* __restrict__ wk, int layer) {
    __shared__ float As[32][36];    // [row][kk]
    __shared__ float Bs[32][132];   // [kk][col] cols 0..63=q, 64..127=k
    int m0 = blockIdx.x * 32;
    const float* wqL = wq + (size_t)layer * D_ * R_;
    const float* wkL = wk + (size_t)layer * D_ * R_;
    int t  = threadIdx.x;
    int cg = t & 15;     // col group: q cols cg*4.., k cols 64+cg*4..
    int rg = t >> 4;     // row group: 4 rows each (rg 0..7)
    float acc[4][8];
    #pragma unroll
    for (int i = 0; i < 4; i++)
        #pragma unroll
        for (int j = 0; j < 8; j++) acc[i][j] = 0.f;

    for (int kc = 0; kc < D_; kc += 32) {
        #pragma unroll
        for (int i = t; i < 32 * 8; i += 128) {
            int row = i >> 3, kq = (i & 7) * 4;
            int gr = m0 + row; if (gr >= M_) gr = M_ - 1;
            float4 v = *(const float4*)&g_val[(size_t)gr * D_ + kc + kq];
            *(float4*)&As[row][kq] = v;
        }
        #pragma unroll
        for (int i = t; i < 32 * 32; i += 128) {
            int kk = i >> 5, c4 = (i & 31) * 4;
            float4 v;
            if (c4 < 64) v = *(const float4*)&wqL[(size_t)(kc + kk) * R_ + c4];
            else         v = *(const float4*)&wkL[(size_t)(kc + kk) * R_ + (c4 - 64)];
            *(float4*)&Bs[kk][c4] = v;
        }
        __syncthreads();
        #pragma unroll 8
        for (int kk = 0; kk < 32; kk++) {
            float a[4];
            #pragma unroll
            for (int i = 0; i < 4; i++) a[i] = As[rg * 4 + i][kk];
            float4 b0 = *(const float4*)&Bs[kk][cg * 4];        // q
            float4 b1 = *(const float4*)&Bs[kk][64 + cg * 4];   // k
            #pragma unroll
            for (int i = 0; i < 4; i++) {
                acc[i][0] += a[i] * b0.x; acc[i][1] += a[i] * b0.y;
                acc[i][2] += a[i] * b0.z; acc[i][3] += a[i] * b0.w;
                acc[i][4] += a[i] * b1.x; acc[i][5] += a[i] * b1.y;
                acc[i][6] += a[i] * b1.z; acc[i][7] += a[i] * b1.w;
            }
        }
        __syncthreads();
    }
    #pragma unroll
    for (int i = 0; i < 4; i++) {
        int gr = m0 + rg * 4 + i;
        if (gr >= M_) continue;
        float4 oq = make_float4(acc[i][0], acc[i][1], acc[i][2], acc[i][3]);
        float4 ok = make_float4(acc[i][4], acc[i][5], acc[i][6], acc[i][7]);
        *(float4*)&g_q[(size_t)gr * R_ + cg * 4] = oq;
        *(float4*)&g_k[(size_t)gr * R_ + cg * 4] = ok;
    }
}

// ---------------- K3: scores + signed-abs softmax + dstate ----------------
__device__ __forceinline__ bool edge_valid(int n, int w) {
    if (w < 65) { int p = n + w - WINW; return (p >= 0) && (p < N_); }
    return n > WINW;
}
__device__ __forceinline__ float sgnf(float s) {
    return (s > 0.f) ? 1.f : ((s < 0.f) ? -1.f : 0.f);
}

#define KS_STR 65
__global__ void k_scores() {
    __shared__ float ks[96][KS_STR];
    __shared__ float qs[32][KS_STR];
    __shared__ float k0[64];
    __shared__ float st[97];
    __shared__ float sc[32][68];
    int b  = blockIdx.y;
    int n0 = blockIdx.x * 32;
    int t  = threadIdx.x;
    size_t base = (size_t)b * N_;

    for (int i = t; i < 96 * 64; i += 256) {
        int r = i >> 6, rr = i & 63;
        int g = n0 - WINW + r; g = min(max(g, 0), N_ - 1);
        ks[r][rr] = g_k[(base + g) * R_ + rr];
    }
    for (int i = t; i < 32 * 64; i += 256) {
        int r = i >> 6, rr = i & 63;
        int g = n0 + r; if (g >= N_) g = N_ - 1;
        qs[r][rr] = g_q[(base + g) * R_ + rr];
    }
    if (t < 64) k0[t] = g_k[base * R_ + t];
    if (t < 96) { int g = min(max(n0 - WINW + t, 0), N_ - 1); st[t] = g_state[base + g]; }
    if (t == 96) st[96] = g_state[base];
    __syncthreads();

    {
        int ng2 = t >> 4;
        int wg  = t & 15;
        int i0 = ng2 * 2, w0 = wg * 4;
        float acc[2][4];
        #pragma unroll
        for (int j = 0; j < 2; j++)
            #pragma unroll
            for (int l = 0; l < 4; l++) acc[j][l] = 0.f;
        #pragma unroll 4
        for (int rr = 0; rr < 64; rr++) {
            float q0 = qs[i0][rr];
            float q1 = qs[i0 + 1][rr];
            float kv[5];
            #pragma unroll
            for (int m = 0; m < 5; m++) kv[m] = ks[i0 + w0 + m][rr];
            #pragma unroll
            for (int l = 0; l < 4; l++) {
                acc[0][l] += q0 * kv[l];
                acc[1][l] += q1 * kv[l + 1];
            }
        }
        #pragma unroll
        for (int l = 0; l < 4; l++) {
            sc[i0][w0 + l]     = acc[0][l] * SCALE;
            sc[i0 + 1][w0 + l] = acc[1][l] * SCALE;
        }
    }
    if (t < 64) {
        int i = t >> 1, w = 64 + (t & 1);
        float acc = 0.f;
        if (w == 64) {
            #pragma unroll 8
            for (int rr = 0; rr < 64; rr++) acc += qs[i][rr] * ks[i + 64][rr];
        } else {
            #pragma unroll 8
            for (int rr = 0; rr < 64; rr++) acc += qs[i][rr] * k0[rr];
        }
        sc[i][w] = acc * SCALE;
    }
    __syncthreads();

    int warp = t >> 5, lane = t & 31;
    for (int i = warp; i < 32; i += 8) {
        int n = n0 + i;
        if (n >= N_) continue;
        int w0 = lane, w1 = lane + 32, w2 = (lane < 2) ? 64 + lane : -1;
        float s0 = sc[i][w0], s1 = sc[i][w1];
        float s2 = (w2 >= 0) ? sc[i][w2] : 0.f;
        bool v0 = edge_valid(n, w0);
        bool v1 = edge_valid(n, w1);
        bool v2 = (w2 >= 0) ? edge_valid(n, w2) : false;
        float mx = fmaxf(v0 ? fabsf(s0) : -1e30f,
                   fmaxf(v1 ? fabsf(s1) : -1e30f,
                         v2 ? fabsf(s2) : -1e30f));
        #pragma unroll
        for (int o = 16; o; o >>= 1) mx = fmaxf(mx, __shfl_xor_sync(0xffffffffu, mx, o));
        float e0 = v0 ? expf(fabsf(s0) - mx) : 0.f;
        float e1 = v1 ? expf(fabsf(s1) - mx) : 0.f;
        float e2 = v2 ? expf(fabsf(s2) - mx) : 0.f;
        float sum = e0 + e1 + e2;
        #pragma unroll
        for (int o = 16; o; o >>= 1) sum += __shfl_xor_sync(0xffffffffu, sum, o);
        float invs = 1.f / sum;
        float we0 = sgnf(s0) * e0 * invs;
        float we1 = sgnf(s1) * e1 * invs;
        float we2 = sgnf(s2) * e2 * invs;
        size_t o_ = (base + n) * E_;
        g_we[o_ + w0] = we0;
        g_we[o_ + w1] = we1;
        if (w2 >= 0) g_we[o_ + w2] = we2;
        float ds = we0 * st[i + w0] + we1 * st[i + w1];
        if (lane == 0) ds += we2 * st[i + 64];
        if (lane == 1) ds += we2 * st[96];
        #pragma unroll
        for (int o = 16; o; o >>= 1) ds += __shfl_xor_sync(0xffffffffu, ds, o);
        if (lane == 0) g_dstate[base + n] = ds;
    }
}

// ---------------- K4: dval propagation (register-blocked, high-occ) ----------------
// block = 64 nodes x 64 feats, 256 threads, thread = 4 nodes x 4 feats
#define DV_NODES 64
#define DV_FEATS 64
#define DV_ROWS  128
#define DV_VSTR  68
#define DV_WSTR  76
// dyn smem: vs[128][68] | wz[64][76] | wa[64] | v0s[64]  = 54784 B
#define DV_SMEM_FLOATS (DV_ROWS*DV_VSTR + DV_NODES*DV_WSTR + DV_NODES + DV_FEATS)

__global__ __launch_bounds__(256, 4) void k_dval() {
    extern __shared__ float sm[];
    float* vs  = sm;                                 // [128][68]
    float* wz  = vs + DV_ROWS * DV_VSTR;             // [64][76], zero-padded
    float* wa  = wz + DV_NODES * DV_WSTR;            // [64]
    float* v0s = wa + DV_NODES;                      // [64]

    int b  = blockIdx.z;
    int dc = blockIdx.y * DV_FEATS;
    int n0 = blockIdx.x * DV_NODES;
    int t  = threadIdx.x;
    size_t base = (size_t)b * N_;

    // stage vs rows (global nodes n0-32+row, clamped): 128 rows x 16 float4
    for (int i = t; i < DV_ROWS * (DV_FEATS / 4); i += 256) {
        int row = i >> 4, c4 = i & 15;
        int g = min(max(n0 - WINW + row, 0), N_ - 1);
        float4 v = *(const float4*)&g_val[(base + g) * D_ + dc + c4 * 4];
        *(float4*)&vs[row * DV_VSTR + c4 * 4] = v;
    }
    for (int i = t; i < DV_NODES * DV_WSTR; i += 256) wz[i] = 0.f;
    if (t < 16) *(float4*)&v0s[t * 4] = *(const float4*)&g_val[base * D_ + dc + t * 4];
    __syncthreads();
    for (int i = t; i < DV_NODES * 65; i += 256) {
        int node = i / 65, w = i % 65;
        int g = n0 + node; if (g >= N_) g = N_ - 1;
        wz[node * DV_WSTR + w + 8] = g_we[(base + g) * E_ + w];
    }
    if (t < DV_NODES) {
        int g = n0 + t; if (g >= N_) g = N_ - 1;
        wa[t] = g_we[(base + g) * E_ + 65];
    }
    __syncthreads();

    int fg = t & 15;          // feat group -> 4 feats
    int ng = t >> 4;          // node group -> 4 nodes
    int i0 = ng * 4;
    int f0 = fg * 4;

    float4 a[4];
    #pragma unroll
    for (int j = 0; j < 4; j++) a[j] = make_float4(0.f, 0.f, 0.f, 0.f);

    // r = i0 + rr; weight for node (i0+j) is wz[i0+j][rr - j + 8]
    #pragma unroll 4
    for (int rr = 0; rr < 68; rr++) {
        float wt[4];
        #pragma unroll
        for (int j = 0; j < 4; j++) wt[j] = wz[(i0 + j) * DV_WSTR + rr - j + 8];
        float4 v = *(const float4*)&vs[(i0 + rr) * DV_VSTR + f0];
        #pragma unroll
        for (int j = 0; j < 4; j++) {
            a[j].x += wt[j] * v.x; a[j].y += wt[j] * v.y;
            a[j].z += wt[j] * v.z; a[j].w += wt[j] * v.w;
        }
    }
    {   // anchor edge
        float4 v = *(const float4*)&v0s[f0];
        #pragma unroll
        for (int j = 0; j < 4; j++) {
            float wt = wa[i0 + j];
            a[j].x += wt * v.x; a[j].y += wt * v.y;
            a[j].z += wt * v.z; a[j].w += wt * v.w;
        }
    }
    #pragma unroll
    for (int j = 0; j < 4; j++) {
        int n = n0 + i0 + j;
        if (n < N_) {
            *(float4*)&g_dval[(base + n) * D_ + dc + f0] = a[j];
        }
    }
}

// ---------------- K5: residual + LayerNorm + state update ----------------
__global__ void k_ln(const float* __restrict__ lng, const float* __restrict__ lnb,
                     int layer, float* __restrict__ out) {
    __shared__ float sh[8];
    int bn = blockIdx.x;
    int t  = threadIdx.x;
    float* vrow = g_val  + (size_t)bn * D_;
    float* drow = g_dval + (size_t)bn * D_;
    const float* g  = lng + (size_t)layer * D_;
    const float* bt = lnb + (size_t)layer * D_;
    float x0 = vrow[t]       + drow[t];
    float x1 = vrow[t + 256] + drow[t + 256];
    float m  = blkSum256(x0 + x1, sh) * (1.f / D_);
    float d0 = x0 - m, d1 = x1 - m;
    float var = blkSum256(d0 * d0 + d1 * d1, sh) * (1.f / D_);
    float inv = rsqrtf(var + 1e-5f);
    float y0 = d0 * inv * g[t]       + bt[t];
    float y1 = d1 * inv * g[t + 256] + bt[t + 256];
    float* vdst = out ? (out + M_ + (size_t)bn * D_) : vrow;
    vdst[t]       = y0;
    vdst[t + 256] = y1;
    if (t == 0) {
        float s = g_state[bn] + g_dstate[bn];
        if (out) out[bn] = s;
        else     g_state[bn] = s;
    }
}

// ---------------- host ----------------
extern "C" void kernel_launch(void* const* d_in, const int* in_sizes, int n_in,
                              void* d_out, int out_size) {
    const int*   ids  = (const int*)  d_in[0];
    const float* emb  = (const float*)d_in[1];
    const float* pos  = (const float*)d_in[2];
    const float* aval = (const float*)d_in[3];
    const float* ast  = (const float*)d_in[4];
    const float* ing  = (const float*)d_in[5];
    const float* inb  = (const float*)d_in[6];
    const float* spw  = (const float*)d_in[7];
    const float* spb  = (const float*)d_in[8];
    const float* wq   = (const float*)d_in[9];
    const float* wk   = (const float*)d_in[10];
    const float* lng  = (const float*)d_in[11];
    const float* lnb  = (const float*)d_in[12];
    float* out = (float*)d_out;

    const int dv_smem = DV_SMEM_FLOATS * 4;
    cudaFuncSetAttribute(k_dval, cudaFuncAttributeMaxDynamicSharedMemorySize, dv_smem);

    k_embed<<<M_, 256>>>(ids, emb, pos, aval, ast, ing, inb, spw, spb);
    for (int l = 0; l < L_; l++) {
        k_proj  <<<(M_ + 31) / 32, 128>>>(wq, wk, l);
        k_scores<<<dim3(65, B_), 256>>>();
        k_dval  <<<dim3((N_ + DV_NODES - 1) / DV_NODES, D_ / DV_FEATS, B_), 256, dv_smem>>>();
        k_ln    <<<M_, 256>>>(lng, lnb, l, (l == L_ - 1) ? out : nullptr);
    }
}